// round 2
// baseline (speedup 1.0000x reference)
#include <cuda_runtime.h>
#include <cuda_fp16.h>
#include <cstdint>

#define N_NODES 100000
#define E_EDGES 1600000
#define IN_CH 64
#define HID 16
#define HEADS 4
#define G_GRAPHS 512
#define NB_ALLOC ((N_NODES + 255) / 256)      // 391
#define NBG1 ((N_NODES + 127) / 128)          // 782 gemm blocks
#define NBH 1536                               // hist blocks

// ---------------- scratch (device globals) ----------------
__device__ int     g_hist[N_NODES];
__device__ int     g_offs[N_NODES];
__device__ int     g_cursor[N_NODES];
__device__ int     g_alloc;
__device__ int     g_ssrc[E_EDGES + N_NODES];
__device__ int     g_is64;

__device__ __half2 g_h1h[N_NODES * 32];        // h1 fp16, 128B/row
__device__ float   g_als1[N_NODES * 4];
__device__ float   g_ald1[N_NODES * 4];
__device__ float   g_h1e[N_NODES * 64];        // post-ELU layer1 out (fp32)
__device__ __half2 g_h2h[N_NODES * 8];         // h2 fp16, 32B/row
__device__ float   g_al2s[N_NODES];
__device__ float   g_al2d[N_NODES];
__device__ float   g_pool[G_GRAPHS * 16];
__device__ float   g_cnt[G_GRAPHS];

// ---------------- K1: gemm1 || hist (role-split) ----------------
__global__ __launch_bounds__(128) void k_pre(
    const float* __restrict__ x, const float* __restrict__ W1,
    const float* __restrict__ a1s, const float* __restrict__ a1d,
    const void* __restrict__ ei) {

    if (blockIdx.x < NBG1) {
        // ---- GEMM1: h1 = x @ W1 (+ attention logits) ----
        __shared__ float ws[64 * 64];
        __shared__ float sas[64], sad[64];
        for (int i = threadIdx.x; i < 4096; i += 128) ws[i] = W1[i];
        if (threadIdx.x < 64) { sas[threadIdx.x] = a1s[threadIdx.x]; sad[threadIdx.x] = a1d[threadIdx.x]; }
        __syncthreads();
        int n = blockIdx.x * 128 + threadIdx.x;
        if (n >= N_NODES) return;

        float xr[64];
        const float4* xp = (const float4*)(x + (size_t)n * 64);
        #pragma unroll
        for (int i = 0; i < 16; i++) {
            float4 v = xp[i];
            xr[4*i] = v.x; xr[4*i+1] = v.y; xr[4*i+2] = v.z; xr[4*i+3] = v.w;
        }
        #pragma unroll 1
        for (int h = 0; h < 4; h++) {
            float acc[16];
            #pragma unroll
            for (int j = 0; j < 16; j++) acc[j] = 0.f;
            #pragma unroll
            for (int k = 0; k < 64; k++) {
                float xv = xr[k];
                #pragma unroll
                for (int j = 0; j < 16; j++)
                    acc[j] = fmaf(xv, ws[k * 64 + h * 16 + j], acc[j]);
            }
            float s = 0.f, d = 0.f;
            #pragma unroll
            for (int j = 0; j < 16; j++) {
                s = fmaf(acc[j], sas[h * 16 + j], s);
                d = fmaf(acc[j], sad[h * 16 + j], d);
            }
            __half2* hp = g_h1h + (size_t)n * 32 + h * 8;
            #pragma unroll
            for (int j = 0; j < 8; j++)
                hp[j] = __floats2half2_rn(acc[2*j], acc[2*j+1]);
            g_als1[n * 4 + h] = s;
            g_ald1[n * 4 + h] = d;
        }
    } else {
        // ---- HIST: count real edges per dst (self-loops added in alloc) ----
        __shared__ int s_is64;
        if (threadIdx.x == 0) {
            const unsigned* w = (const unsigned*)ei;
            int is64 = 1;
            #pragma unroll
            for (int k = 1; k < 64; k += 2) if (w[k] != 0u) is64 = 0;
            s_is64 = is64;
            if (blockIdx.x == NBG1) g_is64 = is64;
        }
        __syncthreads();
        int is64 = s_is64;
        int stride = 128 * NBH;
        for (int i = (blockIdx.x - NBG1) * 128 + threadIdx.x; i < E_EDGES; i += stride) {
            int dst = is64 ? (int)((const long long*)ei)[E_EDGES + i]
                           : ((const int*)ei)[E_EDGES + i];
            atomicAdd(&g_hist[dst], 1);
        }
    }
}

// ---------------- K2: segment allocation (block scan + one atomic) --------
__global__ __launch_bounds__(256) void k_alloc() {
    __shared__ int sh[256];
    __shared__ int sbase;
    int i = blockIdx.x * 256 + threadIdx.x;
    int deg = (i < N_NODES) ? g_hist[i] + 1 : 0;   // +1 self loop
    sh[threadIdx.x] = deg;
    __syncthreads();
    for (int off = 1; off < 256; off <<= 1) {
        int t = (threadIdx.x >= off) ? sh[threadIdx.x - off] : 0;
        __syncthreads();
        sh[threadIdx.x] += t;
        __syncthreads();
    }
    if (threadIdx.x == 255) sbase = atomicAdd(&g_alloc, sh[255]);
    __syncthreads();
    if (i < N_NODES) {
        int base = sbase + sh[threadIdx.x] - deg;
        g_offs[i] = base;
        g_ssrc[base] = i;          // self-loop occupies slot 0
        g_cursor[i] = base + 1;
    }
}

// ---------------- K3: scatter edges by dst ----------------
__global__ __launch_bounds__(256) void k_scatter(const void* __restrict__ ei) {
    int is64 = g_is64;
    int stride = blockDim.x * gridDim.x;
    for (int i = blockIdx.x * blockDim.x + threadIdx.x; i < E_EDGES; i += stride) {
        int src, dst;
        if (is64) {
            src = (int)((const long long*)ei)[i];
            dst = (int)((const long long*)ei)[E_EDGES + i];
        } else {
            src = ((const int*)ei)[i];
            dst = ((const int*)ei)[E_EDGES + i];
        }
        int pos = atomicAdd(&g_cursor[dst], 1);
        g_ssrc[pos] = src;
    }
}

// ---------------- K4: layer-1 aggregation (warp per dst) ----------------
__global__ __launch_bounds__(256) void k_agg1(const float* __restrict__ b1) {
    __shared__ float sb1[64];
    if (threadIdx.x < 64) sb1[threadIdx.x] = b1[threadIdx.x];
    __syncthreads();
    int wid = (blockIdx.x * blockDim.x + threadIdx.x) >> 5;
    int lane = threadIdx.x & 31;
    if (wid >= N_NODES) return;
    int dst = wid;
    int start = g_offs[dst];
    int end   = start + g_hist[dst] + 1;
    int hh = lane >> 3;
    float aldv = g_ald1[dst * 4 + hh];
    float ax = 0.f, ay = 0.f, wsum = 0.f;
    #pragma unroll 2
    for (int k = start; k < end; k++) {
        int src = g_ssrc[k];
        float e = g_als1[src * 4 + hh] + aldv;
        e = e > 0.f ? e : 0.2f * e;
        float w = __expf(e);
        float2 v = __half22float2(g_h1h[(size_t)src * 32 + lane]);
        ax = fmaf(w, v.x, ax);
        ay = fmaf(w, v.y, ay);
        wsum += w;
    }
    float inv = 1.0f / wsum;
    float o0 = ax * inv + sb1[2 * lane];
    float o1 = ay * inv + sb1[2 * lane + 1];
    o0 = o0 > 0.f ? o0 : (__expf(o0) - 1.f);   // ELU
    o1 = o1 > 0.f ? o1 : (__expf(o1) - 1.f);
    *(float2*)(g_h1e + (size_t)dst * 64 + 2 * lane) = make_float2(o0, o1);
}

// ---------------- K5: GEMM2 h2 = h1e @ W2, layer-2 logits ----------------
__global__ __launch_bounds__(128) void k_gemm2(
    const float* __restrict__ W2,
    const float* __restrict__ a2s, const float* __restrict__ a2d) {
    __shared__ float ws[64 * 16];
    __shared__ float s2s[16], s2d[16];
    for (int i = threadIdx.x; i < 1024; i += 128) ws[i] = W2[i];
    if (threadIdx.x < 16) { s2s[threadIdx.x] = a2s[threadIdx.x]; s2d[threadIdx.x] = a2d[threadIdx.x]; }
    __syncthreads();
    int n = blockIdx.x * 128 + threadIdx.x;
    if (n >= N_NODES) return;

    float v[64];
    const float4* vp = (const float4*)(g_h1e + (size_t)n * 64);
    #pragma unroll
    for (int i = 0; i < 16; i++) {
        float4 t = vp[i];
        v[4*i] = t.x; v[4*i+1] = t.y; v[4*i+2] = t.z; v[4*i+3] = t.w;
    }
    float acc[16];
    #pragma unroll
    for (int j = 0; j < 16; j++) acc[j] = 0.f;
    #pragma unroll
    for (int k = 0; k < 64; k++) {
        float xv = v[k];
        #pragma unroll
        for (int j = 0; j < 16; j++)
            acc[j] = fmaf(xv, ws[k * 16 + j], acc[j]);
    }
    float s = 0.f, d = 0.f;
    #pragma unroll
    for (int j = 0; j < 16; j++) {
        s = fmaf(acc[j], s2s[j], s);
        d = fmaf(acc[j], s2d[j], d);
    }
    __half2* hp = g_h2h + (size_t)n * 8;
    #pragma unroll
    for (int j = 0; j < 8; j++)
        hp[j] = __floats2half2_rn(acc[2*j], acc[2*j+1]);
    g_al2s[n] = s;
    g_al2d[n] = d;
}

// ---------------- K6: layer-2 aggregation + pooling (half-warp per dst) ---
__global__ __launch_bounds__(256) void k_agg2(
    const float* __restrict__ b2, const void* __restrict__ batchp) {
    int hw = (blockIdx.x * blockDim.x + threadIdx.x) >> 4;
    int c = threadIdx.x & 15;
    if (hw >= N_NODES) return;
    int dst = hw;
    int start = g_offs[dst];
    int deg   = g_hist[dst] + 1;
    int end   = start + deg;
    float aldv = g_al2d[dst];
    const __half* h2p = (const __half*)g_h2h;
    float acc = 0.f, wsum = 0.f;
    #pragma unroll 2
    for (int k = start; k < end; k++) {
        int src = g_ssrc[k];
        float e = g_al2s[src] + aldv;
        e = e > 0.f ? e : 0.2f * e;
        float w = __expf(e);
        acc = fmaf(w, __half2float(h2p[(size_t)src * 16 + c]), acc);
        wsum += w;
    }
    float o = acc / wsum + b2[c];
    o = o > 0.f ? o : (__expf(o) - 1.f);      // ELU
    int g = g_is64 ? (int)((const long long*)batchp)[dst]
                   : ((const int*)batchp)[dst];
    atomicAdd(&g_pool[g * 16 + c], o);
    if (c == 0) {
        atomicAdd(&g_cnt[g], 1.0f);
        g_hist[dst] = 0;                       // reset for next launch
    }
}

// ---------------- K7: final mean + linear head (+ state reset) ------------
__global__ void k_final(const float* __restrict__ Wc, const float* __restrict__ bc,
                        float* __restrict__ out) {
    int g = threadIdx.x;
    if (g >= G_GRAPHS) return;
    float inv = 1.0f / fmaxf(g_cnt[g], 1.0f);
    float s = 0.f;
    #pragma unroll
    for (int c = 0; c < 16; c++) {
        s = fmaf(g_pool[g * 16 + c] * inv, Wc[c], s);
        g_pool[g * 16 + c] = 0.f;              // reset for next launch
    }
    out[g] = s + bc[0];
    g_cnt[g] = 0.f;
    if (g == 0) g_alloc = 0;
}

// ---------------- launch ----------------
extern "C" void kernel_launch(void* const* d_in, const int* in_sizes, int n_in,
                              void* d_out, int out_size) {
    const float* x    = (const float*)d_in[0];
    const void*  ei   = d_in[1];
    const void*  batch = d_in[2];
    const float* W1   = (const float*)d_in[3];
    const float* a1s  = (const float*)d_in[4];
    const float* a1d  = (const float*)d_in[5];
    const float* b1   = (const float*)d_in[6];
    const float* W2   = (const float*)d_in[7];
    const float* a2s  = (const float*)d_in[8];
    const float* a2d  = (const float*)d_in[9];
    const float* b2   = (const float*)d_in[10];
    const float* Wc   = (const float*)d_in[11];
    const float* bc   = (const float*)d_in[12];
    float* out = (float*)d_out;

    k_pre<<<NBG1 + NBH, 128>>>(x, W1, a1s, a1d, ei);
    k_alloc<<<NB_ALLOC, 256>>>();
    k_scatter<<<2048, 256>>>(ei);
    k_agg1<<<(N_NODES * 32 + 255) / 256, 256>>>(b1);
    k_gemm2<<<(N_NODES + 127) / 128, 128>>>(W2, a2s, a2d);
    k_agg2<<<(N_NODES * 16 + 255) / 256, 256>>>(b2, batch);
    k_final<<<1, 512>>>(Wc, bc, out);
}